// round 14
// baseline (speedup 1.0000x reference)
#include <cuda_runtime.h>
#include <cuda_bf16.h>
#include <cstdint>

// EdgeMLPMPN: out[e] = W3 @ elu(W2 @ elu(W1 @ [x[src];x[tgt]] + b1) + b2) + b3
//   Kernel 1 (tf32 single-pass mma.sync GEMM): [A|B](n) = [W1a|W1b] @ x[n]
//   Kernel 2: warp-specialized pipeline, TF32 single-pass, HALF-TILE barriers:
//       producers w0-3 <-> consumers wm{0,1} (edges 0-63), w4-7 <-> wm{2,3}.
// Compiled at sm_100 (no 'a'): mma.sync only, no tcgen05.

#define C 128
#define NMAX 50000
#define ET 128
#define NBUF 2
#define EDGE_GRID 148
typedef unsigned long long ull;
typedef uint32_t u32;

__device__ float g_A[(size_t)NMAX * C];
__device__ float g_B[(size_t)NMAX * C];

__device__ __forceinline__ float elu_fast(float x) {
    return x > 0.0f ? x : (__expf(x) - 1.0f);
}

__device__ __forceinline__ bool idx_is_i64(const void* p) {
    const ull* q = (const ull*)p;
    unsigned hi = 0;
    #pragma unroll
    for (int i = 0; i < 8; i++) hi |= (unsigned)(q[i] >> 32);
    return hi == 0;
}

__device__ __forceinline__ u32 smem_u32(const void* p) {
    u32 a; asm("{ .reg .u64 t; cvta.to.shared.u64 t, %1; cvt.u32.u64 %0, t; }" : "=r"(a) : "l"(p));
    return a;
}

__device__ __forceinline__ void mma_tf32(float* d, u32 a0, u32 a1, u32 a2, u32 a3,
                                         u32 b0, u32 b1) {
    asm volatile("mma.sync.aligned.m16n8k8.row.col.f32.tf32.tf32.f32 "
                 "{%0,%1,%2,%3}, {%4,%5,%6,%7}, {%8,%9}, {%0,%1,%2,%3};"
                 : "+f"(d[0]), "+f"(d[1]), "+f"(d[2]), "+f"(d[3])
                 : "r"(a0), "r"(a1), "r"(a2), "r"(a3), "r"(b0), "r"(b1));
}

__device__ __forceinline__ u32 cvt_tf32(float f) {
    u32 r; asm("cvt.rna.tf32.f32 %0, %1;" : "=r"(r) : "f"(f));
    return r;
}

// packed dual fp32 add, round-to-nearest (bit-identical to 2x FADD.RN)
__device__ __forceinline__ ull add2(ull a, ull b) {
    ull r; asm("add.rn.f32x2 %0, %1, %2;" : "=l"(r) : "l"(a), "l"(b));
    return r;
}

#define BAR_SYNC(id, n)   asm volatile("bar.sync %0, %1;"   :: "r"(id), "r"(n) : "memory")
#define BAR_ARRIVE(id, n) asm volatile("bar.arrive %0, %1;" :: "r"(id), "r"(n) : "memory")
#define MEMBAR_CTA()      asm volatile("membar.cta;" ::: "memory")

#define WP_STRIDE 544
#define H_STRIDE  528

// ---------------------------------------------------------------------------
// Kernel 1: node precompute, tf32 single-pass MMA GEMM (round-13 proven).
// ---------------------------------------------------------------------------
#define PC_X    0
#define PC_WP   67584
#define PC_SMEM (67584 + 256 * WP_STRIDE)    // 206848

__global__ void __launch_bounds__(512, 1)
precompute_mma_kernel(const float* __restrict__ x, const float* __restrict__ W1, int N)
{
    extern __shared__ __align__(128) char smc[];
    int tid = threadIdx.x;
    int lane = tid & 31, w = tid >> 5;
    int n0 = blockIdx.x * 128;

    for (int idx = tid; idx < 256 * 64; idx += 512) {
        int n = idx >> 6, rest = idx & 63;
        int ks = rest >> 2, q = rest & 3;
        int k0 = ks * 8 + q;
        const float* row = (n < 128) ? (W1 + n * 256) : (W1 + (n - 128) * 256 + 128);
        u32 v0 = cvt_tf32(row[k0]);
        u32 v1 = cvt_tf32(row[k0 + 4]);
        *(ull*)(smc + PC_WP + n * WP_STRIDE + ks * 32 + q * 8) = (ull)v0 | ((ull)v1 << 32);
    }
    for (int idx = tid; idx < 128 * 32; idx += 512) {
        int r = idx >> 5, c4 = idx & 31;
        int n = min(n0 + r, N - 1);
        float4 v = ((const float4*)x)[(size_t)n * 32 + c4];
        uint4 hv;
        hv.x = cvt_tf32(v.x); hv.y = cvt_tf32(v.y);
        hv.z = cvt_tf32(v.z); hv.w = cvt_tf32(v.w);
        *(uint4*)(smc + PC_X + r * H_STRIDE + c4 * 16) = hv;
    }
    __syncthreads();

    int wm = w & 3, wn = w >> 2;
    int lg = lane >> 2;
    int lq = lane & 3;

    u32 bOff = (u32)(PC_WP + (wn * 64 + lg) * WP_STRIDE + lq * 8);
    u32 aOff = (u32)(PC_X + (wm * 32 + lg) * H_STRIDE + lq * 4);

    float acc[2][8][4];
    #pragma unroll
    for (int mi = 0; mi < 2; mi++)
        #pragma unroll
        for (int ni = 0; ni < 8; ni++)
            #pragma unroll
            for (int qq = 0; qq < 4; qq++) acc[mi][ni][qq] = 0.0f;

    #pragma unroll
    for (int ks = 0; ks < 16; ks++) {
        u32 ko = (u32)(ks * 32);
        u32 bb[8][2];
        #pragma unroll
        for (int ni = 0; ni < 8; ni++) {
            ull v = *(const ull*)(smc + bOff + ni * 8 * WP_STRIDE + ko);
            bb[ni][0] = (u32)v; bb[ni][1] = (u32)(v >> 32);
        }
        #pragma unroll
        for (int mi = 0; mi < 2; mi++) {
            u32 ab = aOff + mi * 16 * H_STRIDE + ko;
            u32 a0 = *(const u32*)(smc + ab);
            u32 a2 = *(const u32*)(smc + ab + 16);
            u32 a1 = *(const u32*)(smc + ab + 8 * H_STRIDE);
            u32 a3 = *(const u32*)(smc + ab + 8 * H_STRIDE + 16);
            #pragma unroll
            for (int ni = 0; ni < 8; ni++)
                mma_tf32(acc[mi][ni], a0, a1, a2, a3, bb[ni][0], bb[ni][1]);
        }
    }

    float* dst = (wn < 2) ? g_A : g_B;
    int jbase = (wn & 1) * 64;
    #pragma unroll
    for (int mi = 0; mi < 2; mi++) {
        int r0 = wm * 32 + mi * 16 + lg;
        #pragma unroll
        for (int ni = 0; ni < 8; ni++) {
            int j = jbase + ni * 8 + lq * 2;
            int n_a = n0 + r0, n_b = n0 + r0 + 8;
            if (n_a < N) *(float2*)&dst[(size_t)n_a * C + j] = make_float2(acc[mi][ni][0], acc[mi][ni][1]);
            if (n_b < N) *(float2*)&dst[(size_t)n_b * C + j] = make_float2(acc[mi][ni][2], acc[mi][ni][3]);
        }
    }
}

// ---------------------------------------------------------------------------
// Kernel 2: warp-specialized pipelined edge MLP, TF32, half-tile barriers.
// Barrier ids: READY_LO(b)=1+b, READY_HI(b)=3+b, DONE_LO(b)=5+b, DONE_HI(b)=7+b
//              (all 256 threads); pair(wm)=9+wm (64 threads).
// ---------------------------------------------------------------------------
#define H_TILE    (ET * H_STRIDE)          // 67584
#define OFF_WP    0                        // 69632
#define OFF_H     69632                    // + 2*67584 = 204800
#define OFF_B1    204800
#define OFF_B2    205312
#define OFF_W3    205824
#define OFF_PART  206336                   // 2 parity x 128 f32
#define OFF_B3    208384
#define ED_SMEM   208512

#define NTILES(E) (((E) + ET - 1) / ET)

__global__ void __launch_bounds__(512, 1)
edge_kernel(const void* __restrict__ ei,
            const float* __restrict__ W2, const float* __restrict__ b1,
            const float* __restrict__ b2, const float* __restrict__ W3,
            const float* __restrict__ b3, float* __restrict__ out, int E)
{
    extern __shared__ __align__(128) char smc[];
    u32 sb = smem_u32(smc);
    float* b1s = (float*)(smc + OFF_B1);
    float* b2s = (float*)(smc + OFF_B2);
    float* w3s = (float*)(smc + OFF_W3);
    float* part = (float*)(smc + OFF_PART);

    int tid = threadIdx.x;
    int lane = tid & 31, w = tid >> 5;
    bool i64 = idx_is_i64(ei);

    if (tid < 128) { b1s[tid] = b1[tid]; b2s[tid] = b2[tid]; w3s[tid] = W3[tid]; }
    if (tid == 0) *(float*)(smc + OFF_B3) = b3[0];
    for (int idx = tid; idx < 128 * 64; idx += 512) {
        int n = idx >> 6, rest = idx & 63;
        int ks = rest >> 2, q = rest & 3;
        u32 v0 = cvt_tf32(W2[n * 128 + ks * 8 + q]);
        u32 v1 = cvt_tf32(W2[n * 128 + ks * 8 + q + 4]);
        *(ull*)(smc + OFF_WP + n * WP_STRIDE + ks * 32 + q * 8) = (ull)v0 | ((ull)v1 << 32);
    }
    __syncthreads();

    int ntiles = NTILES(E);

    if (w < 8) {
        // ========== PRODUCERS (256 thr): prefetch-pipelined gather, half-grouped ==========
        int el0 = w * 16;                  // 16 edges per producer warp
        int r = lane >> 3;                 // edge-in-group 0..3
        int q = lane & 7;                  // float4 index within 128B line
        int rdyBase = (w < 4) ? 1 : 3;     // READY_LO / READY_HI
        int dnBase  = (w < 4) ? 5 : 7;     // DONE_LO / DONE_HI
        const float4* b1v = (const float4*)b1s;
        int i = 0;
        for (int t = blockIdx.x; t < ntiles; t += EDGE_GRID, i++) {
            int b = i & 1;
            int myidx;
            {
                int ee = min(t * ET + el0 + (lane & 15), E - 1);
                if (i64) {
                    const long long* qq = (const long long*)ei;
                    myidx = (int)((lane < 16) ? qq[ee] : qq[(size_t)E + ee]);
                } else {
                    const int* qq = (const int*)ei;
                    myidx = (lane < 16) ? qq[ee] : qq[(size_t)E + ee];
                }
            }
            // Prefetch gg=0 gathers into registers BEFORE the buffer-free wait
            float4 av[4], bv[4];
            {
                int s  = __shfl_sync(0xFFFFFFFFu, myidx, r);
                int tg = __shfl_sync(0xFFFFFFFFu, myidx, 16 + r);
                const float4* Ar = (const float4*)g_A + (size_t)s  * 32 + q;
                const float4* Br = (const float4*)g_B + (size_t)tg * 32 + q;
                #pragma unroll
                for (int p = 0; p < 4; p++) { av[p] = Ar[8 * p]; bv[p] = Br[8 * p]; }
            }
            if (i >= NBUF) BAR_SYNC(dnBase + b, 256);
            #pragma unroll
            for (int gg = 0; gg < 4; gg++) {
                float4 nav[4], nbv[4];
                if (gg < 3) {
                    int jn = (gg + 1) * 4 + r;
                    int s  = __shfl_sync(0xFFFFFFFFu, myidx, jn);
                    int tg = __shfl_sync(0xFFFFFFFFu, myidx, 16 + jn);
                    const float4* Ar = (const float4*)g_A + (size_t)s  * 32 + q;
                    const float4* Br = (const float4*)g_B + (size_t)tg * 32 + q;
                    #pragma unroll
                    for (int p = 0; p < 4; p++) { nav[p] = Ar[8 * p]; nbv[p] = Br[8 * p]; }
                }
                int j = gg * 4 + r;
                char* hh = smc + OFF_H + b * H_TILE + (el0 + j) * H_STRIDE + q * 16;
                #pragma unroll
                for (int p = 0; p < 4; p++) {
                    // packed adds: t = a + b + bi  (bit-identical to scalar FADD.RN)
                    ull t01 = add2(add2(((ull*)&av[p])[0], ((ull*)&bv[p])[0]),
                                   ((const ull*)&b1v[q + 8 * p])[0]);
                    ull t23 = add2(add2(((ull*)&av[p])[1], ((ull*)&bv[p])[1]),
                                   ((const ull*)&b1v[q + 8 * p])[1]);
                    float2 f01 = *(float2*)&t01;
                    float2 f23 = *(float2*)&t23;
                    uint4 hv;
                    hv.x = cvt_tf32(elu_fast(f01.x));
                    hv.y = cvt_tf32(elu_fast(f01.y));
                    hv.z = cvt_tf32(elu_fast(f23.x));
                    hv.w = cvt_tf32(elu_fast(f23.y));
                    *(uint4*)(hh + p * 128) = hv;
                }
                if (gg < 3) {
                    #pragma unroll
                    for (int p = 0; p < 4; p++) { av[p] = nav[p]; bv[p] = nbv[p]; }
                }
            }
            MEMBAR_CTA();
            BAR_ARRIVE(rdyBase + b, 256);
        }
    } else {
        // ========== CONSUMERS (256 thr): tf32 MMA + pairwise epilogue, half-grouped ==========
        int cw = w - 8;
        int wm = cw & 3;                  // row block [wm*32,+32)
        int wh = cw >> 2;                 // col half  [wh*64,+64)
        int lg = lane >> 2;
        int lq = lane & 3;
        int rdyBase = (wm < 2) ? 1 : 3;
        int dnBase  = (wm < 2) ? 5 : 7;

        u32 bBase = sb + OFF_WP + (wh * 64 + lg) * WP_STRIDE + lq * 8;

        float b3v = *(float*)(smc + OFF_B3);
        int i = 0;
        for (int t = blockIdx.x; t < ntiles; t += EDGE_GRID, i++) {
            int b = i & 1;

            float acc[2][8][4];
            #pragma unroll
            for (int mi = 0; mi < 2; mi++)
                #pragma unroll
                for (int ni = 0; ni < 8; ni++)
                    #pragma unroll
                    for (int qq = 0; qq < 4; qq++) acc[mi][ni][qq] = 0.0f;

            u32 aBase = sb + OFF_H + b * H_TILE + (wm * 32 + lg) * H_STRIDE + lq * 4;

            // Peel ks=0 B-frag load above the READY wait (W2 is tile-invariant)
            u32 bb[8][2];
            #pragma unroll
            for (int ni = 0; ni < 8; ni++) {
                ull v = *(const ull*)(smc + (bBase - sb) + ni * 8 * WP_STRIDE);
                bb[ni][0] = (u32)v; bb[ni][1] = (u32)(v >> 32);
            }

            BAR_SYNC(rdyBase + b, 256);

            #pragma unroll
            for (int ks = 0; ks < 16; ks++) {
                u32 ko = (u32)(ks * 32);
                if (ks > 0) {
                    #pragma unroll
                    for (int ni = 0; ni < 8; ni++) {
                        ull v = *(const ull*)(smc + (bBase - sb) + ni * 8 * WP_STRIDE + ko);
                        bb[ni][0] = (u32)v; bb[ni][1] = (u32)(v >> 32);
                    }
                }
                #pragma unroll
                for (int mi = 0; mi < 2; mi++) {
                    u32 ab = aBase - sb + mi * 16 * H_STRIDE + ko;
                    u32 a0 = *(const u32*)(smc + ab);
                    u32 a2 = *(const u32*)(smc + ab + 16);
                    u32 a1 = *(const u32*)(smc + ab + 8 * H_STRIDE);
                    u32 a3 = *(const u32*)(smc + ab + 8 * H_STRIDE + 16);
                    #pragma unroll
                    for (int ni = 0; ni < 8; ni++)
                        mma_tf32(acc[mi][ni], a0, a1, a2, a3, bb[ni][0], bb[ni][1]);
                }
            }
            BAR_ARRIVE(dnBase + b, 256);   // half-buffer free; epilogue in regs only

            // Per-row partials: pr[mi][half] reduced over lq
            float pr[2][2];
            #pragma unroll
            for (int mi = 0; mi < 2; mi++) {
                float p0 = 0.0f, p1 = 0.0f;
                #pragma unroll
                for (int ni = 0; ni < 8; ni++) {
                    int j = wh * 64 + ni * 8 + lq * 2;
                    float w3a = w3s[j], w3b = w3s[j + 1];
                    float b2a = b2s[j], b2b = b2s[j + 1];
                    p0 = fmaf(w3a, elu_fast(acc[mi][ni][0] + b2a), p0);
                    p0 = fmaf(w3b, elu_fast(acc[mi][ni][1] + b2b), p0);
                    p1 = fmaf(w3a, elu_fast(acc[mi][ni][2] + b2a), p1);
                    p1 = fmaf(w3b, elu_fast(acc[mi][ni][3] + b2b), p1);
                }
                p0 += __shfl_xor_sync(0xFFFFFFFFu, p0, 1);
                p0 += __shfl_xor_sync(0xFFFFFFFFu, p0, 2);
                p1 += __shfl_xor_sync(0xFFFFFFFFu, p1, 1);
                p1 += __shfl_xor_sync(0xFFFFFFFFu, p1, 2);
                pr[mi][0] = p0; pr[mi][1] = p1;
            }

            int par = i & 1;
            float* pp = part + par * 128;
            if (wh == 1) {
                if (lq == 0) {
                    #pragma unroll
                    for (int mi = 0; mi < 2; mi++) {
                        int rr = wm * 32 + mi * 16 + lg;
                        pp[rr]     = pr[mi][0];
                        pp[rr + 8] = pr[mi][1];
                    }
                }
                BAR_SYNC(9 + wm, 64);      // pair with wh==0 warp of same wm
            } else {
                BAR_SYNC(9 + wm, 64);
                if (lq == 0) {
                    #pragma unroll
                    for (int mi = 0; mi < 2; mi++) {
                        #pragma unroll
                        for (int hf = 0; hf < 2; hf++) {
                            int rr = wm * 32 + mi * 16 + lg + hf * 8;
                            int e = t * ET + rr;
                            if (e < E) out[e] = pr[mi][hf] + pp[rr] + b3v;
                        }
                    }
                }
            }
        }
    }
}

// ---------------------------------------------------------------------------
extern "C" void kernel_launch(void* const* d_in, const int* in_sizes, int n_in,
                              void* d_out, int out_size)
{
    const float* x  = (const float*)d_in[0];
    const void*  ei = d_in[1];
    const float* W1 = (const float*)d_in[2];
    const float* b1 = (const float*)d_in[3];
    const float* W2 = (const float*)d_in[4];
    const float* b2 = (const float*)d_in[5];
    const float* W3 = (const float*)d_in[6];
    const float* b3 = (const float*)d_in[7];
    float* out = (float*)d_out;

    int N = in_sizes[0] / C;        // 50000
    int E = in_sizes[1] / 2;        // 640000

    cudaFuncSetAttribute(precompute_mma_kernel, cudaFuncAttributeMaxDynamicSharedMemorySize, PC_SMEM);
    cudaFuncSetAttribute(edge_kernel,           cudaFuncAttributeMaxDynamicSharedMemorySize, ED_SMEM);

    precompute_mma_kernel<<<(N + 127) / 128, 512, PC_SMEM>>>(x, W1, N);
    edge_kernel<<<EDGE_GRID, 512, ED_SMEM>>>(ei, W2, b1, b2, W3, b3, out, E);
}